// round 16
// baseline (speedup 1.0000x reference)
#include <cuda_runtime.h>
#include <cuda_bf16.h>

#define NC 50000
#define BATCH 128
#define ROWS 768                 // 6 parts * 128
#define DIM 1536                 // 6 * 256
#define N4 12500                 // float4 per row
#define N4Q 3125                 // float4 per quarter-row
#define KE 192                   // K per dist1 item (DIM/8)
#define NCREW 128                // crew blocks (bids 0..127)
#define NPREP 64
#define ND1 512                  // dist1 items: 32 groups x 2 halves x 8 eighths
#define NROWB (ROWS * 4)         // 3072 quarter-row blocks
#define NMEGA (NCREW + NROWB)    // 3200 blocks total

// ---------------- device scratch (no cudaMalloc allowed) ----------------
__device__ float g_part[ROWS][4][6];    // per-quarter partial stats
__device__ float g_tri[2 * BATCH];
__device__ float g_F[BATCH * DIM];      // normalized feat rows, fp32
__device__ __align__(16) __nv_bfloat16 g_TtB[DIM * 256]; // transposed targets
__device__ float g_n2[256];
__device__ float g_dotp[32 * 2 * 8 * 4 * 128]; // [group4][half][eighth][anchor][jl]
__device__ unsigned g_gate1;            // prep-done count (reset by last block)
__device__ unsigned g_work1;            // dist1 steal head (reset by last block)
__device__ unsigned g_done1;            // dist1 items done (reset by last block)
__device__ unsigned g_cnt;              // final counter    (reset by last block)

__device__ __forceinline__ float ex2(float v) {
    float r;
    asm("ex2.approx.ftz.f32 %0, %1;" : "=f"(r) : "f"(v));
    return r;
}

// ============================================================
// ONE kernel. bids 0..127 = crew (prep -> dist1 steal -> dist2), wave-1
// residents whose slots recycle into row blocks as they finish;
// bids 128..3199 = quarter-row blocks (100KB each -> fine-grained packing,
// short drain tail). Row epilogues are computed by the final block.
// ============================================================
__global__ __launch_bounds__(256, 3) void mega_kernel(
    const float* __restrict__ logits, const float* __restrict__ soft,
    const float* __restrict__ ew,     const int*   __restrict__ labels,
    const float* __restrict__ adv,    const int*   __restrict__ mod,
    const float* __restrict__ idf,    const float* __restrict__ gf,
    const int*   __restrict__ epoch_p, float* __restrict__ out)
{
    const int tid = threadIdx.x;
    const int lane = tid & 31, wid = tid >> 5;
    const unsigned full = 0xffffffffu;

    __shared__ __align__(16) float sm[6][8];
    __shared__ __align__(16) float fm[4][8];
    __shared__ bool s_last;

    if (blockIdx.x < NCREW) {
        // ==================== crew path (proven R15) ====================
        const int cid = blockIdx.x;            // 0..127
        __shared__ __align__(16) float As[4][KE];        // 3 KB
        __shared__ __align__(16) float red[8][4][128];   // 16 KB
        __shared__ __align__(16) float wsum[4][8];
        __shared__ float wmax[2][4], wmin[2][4];
        __shared__ int   s_it;

        if (cid < NPREP) {
            // ---- prep item = cid: 4 adjacent target columns ----
            int j0 = cid * 4;
            const float* src = (j0 < BATCH) ? idf : gf;
            int b0 = j0 & 127;

            float v[4][6];
            float sq[4] = {0.f, 0.f, 0.f, 0.f};
#pragma unroll
            for (int p = 0; p < 6; p++)
#pragma unroll
                for (int jj = 0; jj < 4; jj++) {
                    float x = src[(size_t)(p * BATCH + b0 + jj) * 256 + tid];
                    v[jj][p] = x;
                    sq[jj] = fmaf(x, x, sq[jj]);
                }
#pragma unroll
            for (int off = 16; off; off >>= 1)
#pragma unroll
                for (int jj = 0; jj < 4; jj++)
                    sq[jj] += __shfl_down_sync(full, sq[jj], off);
            if (lane == 0)
#pragma unroll
                for (int jj = 0; jj < 4; jj++) wsum[jj][wid] = sq[jj];
            __syncthreads();

            float tot[4], rn[4];
#pragma unroll
            for (int jj = 0; jj < 4; jj++) {
                float t = 0.f;
#pragma unroll
                for (int w = 0; w < 8; w++) t += wsum[jj][w];
                tot[jj] = t;
                rn[jj] = rsqrtf(t);
            }
#pragma unroll
            for (int p = 0; p < 6; p++) {
                int d = p * 256 + tid;
                float nv[4];
#pragma unroll
                for (int jj = 0; jj < 4; jj++) nv[jj] = v[jj][p] * rn[jj];
                __nv_bfloat162 lo = __floats2bfloat162_rn(nv[0], nv[1]);
                __nv_bfloat162 hi = __floats2bfloat162_rn(nv[2], nv[3]);
                uint2 pk;
                pk.x = *(unsigned*)&lo;
                pk.y = *(unsigned*)&hi;
                *(uint2*)&g_TtB[(size_t)d * 256 + j0] = pk;
                if (j0 < BATCH) {
#pragma unroll
                    for (int jj = 0; jj < 4; jj++)
                        g_F[(size_t)(b0 + jj) * DIM + d] = nv[jj];
                }
            }
            if (tid < 4) g_n2[j0 + tid] = tot[tid] * rn[tid] * rn[tid];

            __syncthreads();
            if (tid == 0) { __threadfence(); atomicAdd(&g_gate1, 1u); }
        }

        if (tid == 0) {
            while (*((volatile unsigned*)&g_gate1) < (unsigned)NPREP) { }
            __threadfence();
        }
        __syncthreads();

        // ---- steal dist1 items: (group of 4 anchors) x half x K-eighth ----
        while (true) {
            if (tid == 0) s_it = (int)atomicAdd(&g_work1, 1u);
            __syncthreads();
            int it = s_it;
            if (it >= ND1) break;

            int g4 = it >> 4;
            int h  = (it >> 3) & 1;
            int q  = it & 7;
            int i0 = g4 * 4;
            int k0 = q * KE;

#pragma unroll
            for (int u = 0; u < 3; u++) {
                int idx = tid + u * 256;
                int a  = idx / KE;
                int kk = idx - a * KE;
                As[a][kk] = g_F[(size_t)(i0 + a) * DIM + k0 + kk];
            }
            __syncthreads();

            const uint2* T2 = (const uint2*)g_TtB;
            const int ks = wid * 24;
            const uint2* Tp = T2 + (size_t)(k0 + ks) * 64 + (h * 32 + lane);

            float c[4][4];
#pragma unroll
            for (int a = 0; a < 4; a++)
#pragma unroll
                for (int t = 0; t < 4; t++) c[a][t] = 0.f;

#pragma unroll 1
            for (int kk = 0; kk < 24; kk += 8) {
                uint2 t[8];
#pragma unroll
                for (int u = 0; u < 8; u++) t[u] = Tp[(size_t)(kk + u) * 64];
#pragma unroll
                for (int u = 0; u < 8; u++) {
                    float f0 = __uint_as_float(t[u].x << 16);
                    float f1 = __uint_as_float(t[u].x & 0xffff0000u);
                    float f2 = __uint_as_float(t[u].y << 16);
                    float f3 = __uint_as_float(t[u].y & 0xffff0000u);
                    int k = ks + kk + u;
#pragma unroll
                    for (int a = 0; a < 4; a++) {
                        float A = As[a][k];
                        c[a][0] = fmaf(A, f0, c[a][0]);
                        c[a][1] = fmaf(A, f1, c[a][1]);
                        c[a][2] = fmaf(A, f2, c[a][2]);
                        c[a][3] = fmaf(A, f3, c[a][3]);
                    }
                }
            }
#pragma unroll
            for (int a = 0; a < 4; a++)
                ((float4*)red[wid][a])[lane] =
                    make_float4(c[a][0], c[a][1], c[a][2], c[a][3]);
            __syncthreads();

#pragma unroll
            for (int u = 0; u < 2; u++) {
                int idx = tid + u * 256;
                int a  = idx >> 7;
                int jl = idx & 127;
                float dot = 0.f;
#pragma unroll
                for (int sl = 0; sl < 8; sl++) dot += red[sl][a][jl];
                g_dotp[(((size_t)(g4 * 2 + h) * 8 + q) * 4 + a) * 128 + jl] = dot;
            }
            __syncthreads();
            if (tid == 0) { __threadfence(); atomicAdd(&g_done1, 1u); }
        }

        if (tid == 0) {
            while (*((volatile unsigned*)&g_done1) < (unsigned)ND1) { }
            __threadfence();
        }
        __syncthreads();

        {
            int i  = cid;
            int g4 = i >> 2, a = i & 3;
            int h  = tid >> 7;
            int jl = tid & 127;
            int jglob = h * 128 + jl;

            float dot = 0.f;
#pragma unroll
            for (int q = 0; q < 8; q++)
                dot += g_dotp[(((size_t)(g4 * 2 + h) * 8 + q) * 4 + a) * 128 + jl];

            float sqv = g_n2[i] + g_n2[jglob] - 2.f * dot;
            float dj  = sqrtf(fmaxf(sqv, 0.f) + 1e-12f);

            bool eq  = (labels[i] == labels[jl]);
            bool pos = h ? eq : (eq && (jl != i));
            float apv = pos   ? dj : -1e30f;
            float anv = (!eq) ? dj :  1e30f;
#pragma unroll
            for (int off = 16; off; off >>= 1) {
                apv = fmaxf(apv, __shfl_down_sync(full, apv, off));
                anv = fminf(anv, __shfl_down_sync(full, anv, off));
            }
            if (lane == 0) { wmax[h][wid & 3] = apv; wmin[h][wid & 3] = anv; }
            __syncthreads();

            if ((tid & 127) == 0) {
                float apm = fmaxf(fmaxf(wmax[h][0], wmax[h][1]),
                                  fmaxf(wmax[h][2], wmax[h][3]));
                float anm = fminf(fminf(wmin[h][0], wmin[h][1]),
                                  fminf(wmin[h][2], wmin[h][3]));
                float dap = (apm > -1e29f) ? apm : 0.f;
                float dan = (anm <  1e29f) ? anm : 1e6f;
                g_tri[h * BATCH + i] = fmaxf(dap - dan + 0.3f, 0.f);
            }
        }
    } else {
        // ==================== quarter-row path ====================
        const int rq = blockIdx.x - NCREW;      // 0..3071
        const int r = rq >> 2, q = rq & 3;
        const float4* lg4 = (const float4*)(logits + (size_t)r * NC) + q * N4Q;
        const float4* sf4 = (const float4*)(soft   + (size_t)r * NC) + q * N4Q;
        const float C = 0.48089834696298783f;   // log2(e)/3

        float4 vs1 = {0,0,0,0}, vs2 = {0,0,0,0}, vsx = {0,0,0,0};
        float4 vss = {0,0,0,0}, vssx = {0,0,0,0}, vssl = {0,0,0,0};

#define ACC(xx, sv_, L)                                               \
    {   float x = xx, sv = sv_;                                       \
        vsx.L += x;  vss.L += sv;                                     \
        vssx.L = fmaf(sv, x, vssx.L);                                 \
        vssl.L = fmaf(sv, __log2f(fmaxf(sv, 1e-38f)), vssl.L);        \
        float e = ex2(x * C);                                         \
        vs2.L += e;                                                   \
        vs1.L = fmaf(e * e, e, vs1.L); }
#define LANE4(x4, t4) ACC(x4.x, t4.x, x) ACC(x4.y, t4.y, y) \
                      ACC(x4.z, t4.z, z) ACC(x4.w, t4.w, w)

        int i = tid;
        for (; i + 768 < N4Q; i += 1024) {
            float4 x0 = __ldcs(lg4 + i);
            float4 x1 = __ldcs(lg4 + i + 256);
            float4 x2 = __ldcs(lg4 + i + 512);
            float4 x3 = __ldcs(lg4 + i + 768);
            float4 t0 = __ldcs(sf4 + i);
            float4 t1 = __ldcs(sf4 + i + 256);
            float4 t2 = __ldcs(sf4 + i + 512);
            float4 t3 = __ldcs(sf4 + i + 768);
            LANE4(x0, t0) LANE4(x1, t1) LANE4(x2, t2) LANE4(x3, t3)
        }
        for (; i < N4Q; i += 256) {
            float4 x0 = __ldcs(lg4 + i);
            float4 t0 = __ldcs(sf4 + i);
            LANE4(x0, t0)
        }
#undef LANE4
#undef ACC

        float s1  = (vs1.x + vs1.y) + (vs1.z + vs1.w);
        float s2  = (vs2.x + vs2.y) + (vs2.z + vs2.w);
        float sx  = (vsx.x + vsx.y) + (vsx.z + vsx.w);
        float ssv = (vss.x + vss.y) + (vss.z + vss.w);
        float ssx = (vssx.x + vssx.y) + (vssx.z + vssx.w);
        float ssl = (vssl.x + vssl.y) + (vssl.z + vssl.w);

#pragma unroll
        for (int off = 16; off; off >>= 1) {
            s1  += __shfl_down_sync(full, s1,  off);
            s2  += __shfl_down_sync(full, s2,  off);
            sx  += __shfl_down_sync(full, sx,  off);
            ssv += __shfl_down_sync(full, ssv, off);
            ssx += __shfl_down_sync(full, ssx, off);
            ssl += __shfl_down_sync(full, ssl, off);
        }
        if (lane == 0) {
            sm[0][wid] = s1;  sm[1][wid] = s2;  sm[2][wid] = sx;
            sm[3][wid] = ssv; sm[4][wid] = ssx; sm[5][wid] = ssl;
        }
        __syncthreads();

        if (tid == 0) {
#pragma unroll
            for (int k = 0; k < 6; k++) {
                float acc = 0.f;
#pragma unroll
                for (int w = 0; w < 8; w++) acc += sm[k][w];
                g_part[r][q][k] = acc;
            }
        }
    }

    // ================= last-block-done: epilogues + final reduce ==========
    __syncthreads();
    if (tid == 0) {
        __threadfence();
        unsigned v = atomicAdd(&g_cnt, 1u);
        s_last = (v == (unsigned)(NMEGA - 1));
    }
    __syncthreads();
    if (!s_last) return;
    if (tid == 0) {
        g_cnt = 0; g_gate1 = 0; g_work1 = 0; g_done1 = 0;
        __threadfence();
    }

    float ceA = 0.f, klwA = 0.f, tri0 = 0.f, tri1 = 0.f;
    for (int r = tid; r < ROWS; r += 256) {
        float s1 = 0.f, s2 = 0.f, sx = 0.f, ssv = 0.f, ssx = 0.f, ssl = 0.f;
#pragma unroll
        for (int q = 0; q < 4; q++) {
            s1  += g_part[r][q][0]; s2  += g_part[r][q][1];
            sx  += g_part[r][q][2]; ssv += g_part[r][q][3];
            ssx += g_part[r][q][4]; ssl += g_part[r][q][5];
        }
        float logZ1 = __logf(s1);
        float logZ2 = __logf(s2);

        int   b   = r & (BATCH - 1);
        int   lab = labels[b];
        float xl  = logits[(size_t)r * NC + lab];
        float ce  = logZ1 - 0.9f * xl - 0.1f * sx * (1.f / (float)NC);

        float l0 = adv[2 * r], l1 = adv[2 * r + 1];
        float mm = fmaxf(l0, l1);
        float lse = mm + __logf(__expf(l0 - mm) + __expf(l1 - mm));
        float anll = lse - (mod[b] ? l1 : l0);
        ceA += ce + 0.1f * anll;

        float kl = ssl * 0.6931471805599453f - ssx * (1.f / 3.f) + logZ2 * ssv;
        klwA += fminf(kl, 5.0f) * ew[r];
    }
    if (tid < BATCH) { tri0 = g_tri[tid]; tri1 = g_tri[BATCH + tid]; }

#pragma unroll
    for (int off = 16; off; off >>= 1) {
        ceA  += __shfl_down_sync(full, ceA,  off);
        klwA += __shfl_down_sync(full, klwA, off);
        tri0 += __shfl_down_sync(full, tri0, off);
        tri1 += __shfl_down_sync(full, tri1, off);
    }
    if (lane == 0) {
        fm[0][wid] = ceA; fm[1][wid] = klwA; fm[2][wid] = tri0; fm[3][wid] = tri1;
    }
    __syncthreads();

    if (tid == 0) {
        float ceT = 0.f, klwT = 0.f, t0 = 0.f, t1 = 0.f;
#pragma unroll
        for (int w = 0; w < 8; w++) {
            ceT += fm[0][w]; klwT += fm[1][w]; t0 += fm[2][w]; t1 += fm[3][w];
        }
        float L_idadv = ceT * (1.f / (float)ROWS);   // includes 0.1*L_adv
        float L_tri   = (t0 + 0.5f * t1) * (1.f / (float)BATCH);
        float L_graph = (epoch_p[0] >= 20) ? klwT * (9.f / (float)ROWS) : 0.f;
        out[0] = L_idadv + L_tri + 0.1f * L_graph;
    }
}

// ============================================================
extern "C" void kernel_launch(void* const* d_in, const int* in_sizes, int n_in,
                              void* d_out, int out_size)
{
    const float* id_logits     = (const float*)d_in[0];
    const float* id_features   = (const float*)d_in[1];
    const float* gray_features = (const float*)d_in[2];
    const float* soft_labels   = (const float*)d_in[3];
    const float* entropy_w     = (const float*)d_in[4];
    const float* adv_logits    = (const float*)d_in[5];
    const int*   labels        = (const int*)d_in[6];
    const int*   mod_labels    = (const int*)d_in[7];
    const int*   epoch         = (const int*)d_in[8];

    mega_kernel<<<NMEGA, 256>>>(id_logits, soft_labels, entropy_w, labels,
                                adv_logits, mod_labels,
                                id_features, gray_features,
                                epoch, (float*)d_out);
}

// round 17
// speedup vs baseline: 1.0810x; 1.0810x over previous
#include <cuda_runtime.h>
#include <cuda_bf16.h>

#define NC 50000
#define BATCH 128
#define ROWS 768                 // 6 parts * 128
#define DIM 1536                 // 6 * 256
#define N4 12500                 // float4 per row
#define KE 192                   // K per dist1 item (DIM/8)
#define NCREW 64                 // crew blocks (bids 0..63)
#define NPREP 64
#define ND1 512                  // dist1 items: 32 groups x 2 halves x 8 eighths
#define NMEGA (NCREW + ROWS)     // 832 blocks total

// ---------------- device scratch (no cudaMalloc allowed) ----------------
__device__ float g_ce[ROWS];            // ce + 0.1*adv_nll per row
__device__ float g_klw[ROWS];
__device__ float g_tri[2 * BATCH];
__device__ float g_F[BATCH * DIM];      // normalized feat rows, fp32
__device__ __align__(16) __nv_bfloat16 g_TtB[DIM * 256]; // transposed targets
__device__ float g_n2[256];
__device__ float g_dotp[32 * 2 * 8 * 4 * 128]; // [group4][half][eighth][anchor][jl]
__device__ unsigned g_gate1;            // prep-done count (reset by last block)
__device__ unsigned g_work1;            // dist1 steal head (reset by last block)
__device__ unsigned g_done1;            // dist1 items done (reset by last block)
__device__ unsigned g_cnt;              // final counter    (reset by last block)

__device__ __forceinline__ float ex2(float v) {
    float r;
    asm("ex2.approx.ftz.f32 %0, %1;" : "=f"(r) : "f"(v));
    return r;
}

// ============================================================
// ONE kernel. bids 0..63 = crew (prep -> dist1 steal -> 2x dist2): only 64
// wave-1 slots stolen from the row stream, crew L2 draw spread over a longer
// window (still finishes well under the ~50us row stream);
// bids 64..831 = full-row path (HBM-bound, proven R15 shape).
// Last finished block does the final scalar reduce and resets counters.
// ============================================================
__global__ __launch_bounds__(256, 3) void mega_kernel(
    const float* __restrict__ logits, const float* __restrict__ soft,
    const float* __restrict__ ew,     const int*   __restrict__ labels,
    const float* __restrict__ adv,    const int*   __restrict__ mod,
    const float* __restrict__ idf,    const float* __restrict__ gf,
    const int*   __restrict__ epoch_p, float* __restrict__ out)
{
    const int tid = threadIdx.x;
    const int lane = tid & 31, wid = tid >> 5;
    const unsigned full = 0xffffffffu;

    __shared__ __align__(16) float sm[6][8];
    __shared__ __align__(16) float fm[4][8];
    __shared__ bool s_last;

    if (blockIdx.x < NCREW) {
        // ==================== crew path ====================
        const int cid = blockIdx.x;            // 0..63
        __shared__ __align__(16) float As[4][KE];        // 3 KB
        __shared__ __align__(16) float red[8][4][128];   // 16 KB
        __shared__ __align__(16) float wsum[4][8];
        __shared__ float wmax[2][4], wmin[2][4];
        __shared__ int   s_it;

        {
            // ---- prep item = cid: 4 adjacent target columns ----
            int j0 = cid * 4;
            const float* src = (j0 < BATCH) ? idf : gf;
            int b0 = j0 & 127;

            float v[4][6];
            float sq[4] = {0.f, 0.f, 0.f, 0.f};
#pragma unroll
            for (int p = 0; p < 6; p++)
#pragma unroll
                for (int jj = 0; jj < 4; jj++) {
                    float x = src[(size_t)(p * BATCH + b0 + jj) * 256 + tid];
                    v[jj][p] = x;
                    sq[jj] = fmaf(x, x, sq[jj]);
                }
#pragma unroll
            for (int off = 16; off; off >>= 1)
#pragma unroll
                for (int jj = 0; jj < 4; jj++)
                    sq[jj] += __shfl_down_sync(full, sq[jj], off);
            if (lane == 0)
#pragma unroll
                for (int jj = 0; jj < 4; jj++) wsum[jj][wid] = sq[jj];
            __syncthreads();

            float tot[4], rn[4];
#pragma unroll
            for (int jj = 0; jj < 4; jj++) {
                float t = 0.f;
#pragma unroll
                for (int w = 0; w < 8; w++) t += wsum[jj][w];
                tot[jj] = t;
                rn[jj] = rsqrtf(t);
            }
#pragma unroll
            for (int p = 0; p < 6; p++) {
                int d = p * 256 + tid;
                float nv[4];
#pragma unroll
                for (int jj = 0; jj < 4; jj++) nv[jj] = v[jj][p] * rn[jj];
                __nv_bfloat162 lo = __floats2bfloat162_rn(nv[0], nv[1]);
                __nv_bfloat162 hi = __floats2bfloat162_rn(nv[2], nv[3]);
                uint2 pk;
                pk.x = *(unsigned*)&lo;
                pk.y = *(unsigned*)&hi;
                *(uint2*)&g_TtB[(size_t)d * 256 + j0] = pk;
                if (j0 < BATCH) {
#pragma unroll
                    for (int jj = 0; jj < 4; jj++)
                        g_F[(size_t)(b0 + jj) * DIM + d] = nv[jj];
                }
            }
            if (tid < 4) g_n2[j0 + tid] = tot[tid] * rn[tid] * rn[tid];

            __syncthreads();
            if (tid == 0) { __threadfence(); atomicAdd(&g_gate1, 1u); }
        }

        // ---- wait for all prep ----
        if (tid == 0) {
            while (*((volatile unsigned*)&g_gate1) < (unsigned)NPREP) { }
            __threadfence();
        }
        __syncthreads();

        // ---- steal dist1 items: (group of 4 anchors) x half x K-eighth ----
        while (true) {
            if (tid == 0) s_it = (int)atomicAdd(&g_work1, 1u);
            __syncthreads();
            int it = s_it;
            if (it >= ND1) break;

            int g4 = it >> 4;
            int h  = (it >> 3) & 1;
            int q  = it & 7;
            int i0 = g4 * 4;
            int k0 = q * KE;

#pragma unroll
            for (int u = 0; u < 3; u++) {
                int idx = tid + u * 256;
                int a  = idx / KE;
                int kk = idx - a * KE;
                As[a][kk] = g_F[(size_t)(i0 + a) * DIM + k0 + kk];
            }
            __syncthreads();

            const uint2* T2 = (const uint2*)g_TtB;
            const int ks = wid * 24;
            const uint2* Tp = T2 + (size_t)(k0 + ks) * 64 + (h * 32 + lane);

            float c[4][4];
#pragma unroll
            for (int a = 0; a < 4; a++)
#pragma unroll
                for (int t = 0; t < 4; t++) c[a][t] = 0.f;

#pragma unroll 1
            for (int kk = 0; kk < 24; kk += 8) {
                uint2 t[8];
#pragma unroll
                for (int u = 0; u < 8; u++) t[u] = Tp[(size_t)(kk + u) * 64];
#pragma unroll
                for (int u = 0; u < 8; u++) {
                    float f0 = __uint_as_float(t[u].x << 16);
                    float f1 = __uint_as_float(t[u].x & 0xffff0000u);
                    float f2 = __uint_as_float(t[u].y << 16);
                    float f3 = __uint_as_float(t[u].y & 0xffff0000u);
                    int k = ks + kk + u;
#pragma unroll
                    for (int a = 0; a < 4; a++) {
                        float A = As[a][k];
                        c[a][0] = fmaf(A, f0, c[a][0]);
                        c[a][1] = fmaf(A, f1, c[a][1]);
                        c[a][2] = fmaf(A, f2, c[a][2]);
                        c[a][3] = fmaf(A, f3, c[a][3]);
                    }
                }
            }
#pragma unroll
            for (int a = 0; a < 4; a++)
                ((float4*)red[wid][a])[lane] =
                    make_float4(c[a][0], c[a][1], c[a][2], c[a][3]);
            __syncthreads();

#pragma unroll
            for (int u = 0; u < 2; u++) {
                int idx = tid + u * 256;
                int a  = idx >> 7;
                int jl = idx & 127;
                float dot = 0.f;
#pragma unroll
                for (int sl = 0; sl < 8; sl++) dot += red[sl][a][jl];
                g_dotp[(((size_t)(g4 * 2 + h) * 8 + q) * 4 + a) * 128 + jl] = dot;
            }
            __syncthreads();
            if (tid == 0) { __threadfence(); atomicAdd(&g_done1, 1u); }
        }

        // ---- wait for all dist1, then 2 dist2 anchors ----
        if (tid == 0) {
            while (*((volatile unsigned*)&g_done1) < (unsigned)ND1) { }
            __threadfence();
        }
        __syncthreads();

#pragma unroll
        for (int sub = 0; sub < 2; sub++) {
            int i  = cid * 2 + sub;         // anchor 0..127
            int g4 = i >> 2, a = i & 3;
            int h  = tid >> 7;
            int jl = tid & 127;
            int jglob = h * 128 + jl;

            float dot = 0.f;
#pragma unroll
            for (int q = 0; q < 8; q++)
                dot += g_dotp[(((size_t)(g4 * 2 + h) * 8 + q) * 4 + a) * 128 + jl];

            float sqv = g_n2[i] + g_n2[jglob] - 2.f * dot;
            float dj  = sqrtf(fmaxf(sqv, 0.f) + 1e-12f);

            bool eq  = (labels[i] == labels[jl]);
            bool pos = h ? eq : (eq && (jl != i));
            float apv = pos   ? dj : -1e30f;
            float anv = (!eq) ? dj :  1e30f;
#pragma unroll
            for (int off = 16; off; off >>= 1) {
                apv = fmaxf(apv, __shfl_down_sync(full, apv, off));
                anv = fminf(anv, __shfl_down_sync(full, anv, off));
            }
            if (lane == 0) { wmax[h][wid & 3] = apv; wmin[h][wid & 3] = anv; }
            __syncthreads();

            if ((tid & 127) == 0) {
                float apm = fmaxf(fmaxf(wmax[h][0], wmax[h][1]),
                                  fmaxf(wmax[h][2], wmax[h][3]));
                float anm = fminf(fminf(wmin[h][0], wmin[h][1]),
                                  fminf(wmin[h][2], wmin[h][3]));
                float dap = (apm > -1e29f) ? apm : 0.f;
                float dan = (anm <  1e29f) ? anm : 1e6f;
                g_tri[h * BATCH + i] = fmaxf(dap - dan + 0.3f, 0.f);
                __threadfence();
            }
            __syncthreads();
        }
    } else {
        // ==================== row path (proven R15 shape) ====================
        const int r = blockIdx.x - NCREW;
        const float4* lg4 = (const float4*)(logits + (size_t)r * NC);
        const float4* sf4 = (const float4*)(soft   + (size_t)r * NC);
        const float C = 0.48089834696298783f;   // log2(e)/3

        float4 vs1 = {0,0,0,0}, vs2 = {0,0,0,0}, vsx = {0,0,0,0};
        float4 vss = {0,0,0,0}, vssx = {0,0,0,0}, vssl = {0,0,0,0};

#define ACC(xx, sv_, L)                                               \
    {   float x = xx, sv = sv_;                                       \
        vsx.L += x;  vss.L += sv;                                     \
        vssx.L = fmaf(sv, x, vssx.L);                                 \
        vssl.L = fmaf(sv, __log2f(fmaxf(sv, 1e-38f)), vssl.L);        \
        float e = ex2(x * C);                                         \
        vs2.L += e;                                                   \
        vs1.L = fmaf(e * e, e, vs1.L); }
#define LANE4(x4, t4) ACC(x4.x, t4.x, x) ACC(x4.y, t4.y, y) \
                      ACC(x4.z, t4.z, z) ACC(x4.w, t4.w, w)

        int i = tid;
        for (; i + 768 < N4; i += 1024) {
            float4 x0 = __ldcs(lg4 + i);
            float4 x1 = __ldcs(lg4 + i + 256);
            float4 x2 = __ldcs(lg4 + i + 512);
            float4 x3 = __ldcs(lg4 + i + 768);
            float4 t0 = __ldcs(sf4 + i);
            float4 t1 = __ldcs(sf4 + i + 256);
            float4 t2 = __ldcs(sf4 + i + 512);
            float4 t3 = __ldcs(sf4 + i + 768);
            LANE4(x0, t0) LANE4(x1, t1) LANE4(x2, t2) LANE4(x3, t3)
        }
        for (; i < N4; i += 256) {
            float4 x0 = __ldcs(lg4 + i);
            float4 t0 = __ldcs(sf4 + i);
            LANE4(x0, t0)
        }
#undef LANE4
#undef ACC

        float s1  = (vs1.x + vs1.y) + (vs1.z + vs1.w);
        float s2  = (vs2.x + vs2.y) + (vs2.z + vs2.w);
        float sx  = (vsx.x + vsx.y) + (vsx.z + vsx.w);
        float ssv = (vss.x + vss.y) + (vss.z + vss.w);
        float ssx = (vssx.x + vssx.y) + (vssx.z + vssx.w);
        float ssl = (vssl.x + vssl.y) + (vssl.z + vssl.w);

#pragma unroll
        for (int off = 16; off; off >>= 1) {
            s1  += __shfl_down_sync(full, s1,  off);
            s2  += __shfl_down_sync(full, s2,  off);
            sx  += __shfl_down_sync(full, sx,  off);
            ssv += __shfl_down_sync(full, ssv, off);
            ssx += __shfl_down_sync(full, ssx, off);
            ssl += __shfl_down_sync(full, ssl, off);
        }
        if (lane == 0) {
            sm[0][wid] = s1;  sm[1][wid] = s2;  sm[2][wid] = sx;
            sm[3][wid] = ssv; sm[4][wid] = ssx; sm[5][wid] = ssl;
        }
        __syncthreads();

        if (tid == 0) {
            s1 = 0.f; s2 = 0.f; sx = 0.f; ssv = 0.f; ssx = 0.f; ssl = 0.f;
#pragma unroll
            for (int w = 0; w < 8; w++) {
                s1 += sm[0][w]; s2 += sm[1][w]; sx += sm[2][w];
                ssv += sm[3][w]; ssx += sm[4][w]; ssl += sm[5][w];
            }
            float logZ1 = __logf(s1);
            float logZ2 = __logf(s2);

            int   b   = r & (BATCH - 1);
            int   lab = labels[b];
            float xl  = logits[(size_t)r * NC + lab];
            float ce  = logZ1 - 0.9f * xl - 0.1f * sx * (1.f / (float)NC);

            float l0 = adv[2 * r], l1 = adv[2 * r + 1];
            float mm = fmaxf(l0, l1);
            float lse = mm + __logf(__expf(l0 - mm) + __expf(l1 - mm));
            float anll = lse - (mod[b] ? l1 : l0);
            g_ce[r] = ce + 0.1f * anll;

            float kl = ssl * 0.6931471805599453f - ssx * (1.f / 3.f) + logZ2 * ssv;
            g_klw[r] = fminf(kl, 5.0f) * ew[r];
            __threadfence();
        }
    }

    // ================= last-block-done final reduce =================
    __syncthreads();
    if (tid == 0) {
        unsigned v = atomicAdd(&g_cnt, 1u);
        s_last = (v == (unsigned)(NMEGA - 1));
    }
    __syncthreads();
    if (!s_last) return;
    if (tid == 0) {
        g_cnt = 0; g_gate1 = 0; g_work1 = 0; g_done1 = 0;
        __threadfence();
    }

    float ceA = 0.f, klwA = 0.f, tri0 = 0.f, tri1 = 0.f;
    for (int r = tid; r < ROWS; r += 256) {
        ceA  += g_ce[r];
        klwA += g_klw[r];
    }
    if (tid < BATCH) { tri0 = g_tri[tid]; tri1 = g_tri[BATCH + tid]; }

#pragma unroll
    for (int off = 16; off; off >>= 1) {
        ceA  += __shfl_down_sync(full, ceA,  off);
        klwA += __shfl_down_sync(full, klwA, off);
        tri0 += __shfl_down_sync(full, tri0, off);
        tri1 += __shfl_down_sync(full, tri1, off);
    }
    if (lane == 0) {
        fm[0][wid] = ceA; fm[1][wid] = klwA; fm[2][wid] = tri0; fm[3][wid] = tri1;
    }
    __syncthreads();

    if (tid == 0) {
        float ceT = 0.f, klwT = 0.f, t0 = 0.f, t1 = 0.f;
#pragma unroll
        for (int w = 0; w < 8; w++) {
            ceT += fm[0][w]; klwT += fm[1][w]; t0 += fm[2][w]; t1 += fm[3][w];
        }
        float L_idadv = ceT * (1.f / (float)ROWS);   // includes 0.1*L_adv
        float L_tri   = (t0 + 0.5f * t1) * (1.f / (float)BATCH);
        float L_graph = (epoch_p[0] >= 20) ? klwT * (9.f / (float)ROWS) : 0.f;
        out[0] = L_idadv + L_tri + 0.1f * L_graph;
    }
}

// ============================================================
extern "C" void kernel_launch(void* const* d_in, const int* in_sizes, int n_in,
                              void* d_out, int out_size)
{
    const float* id_logits     = (const float*)d_in[0];
    const float* id_features   = (const float*)d_in[1];
    const float* gray_features = (const float*)d_in[2];
    const float* soft_labels   = (const float*)d_in[3];
    const float* entropy_w     = (const float*)d_in[4];
    const float* adv_logits    = (const float*)d_in[5];
    const int*   labels        = (const int*)d_in[6];
    const int*   mod_labels    = (const int*)d_in[7];
    const int*   epoch         = (const int*)d_in[8];

    mega_kernel<<<NMEGA, 256>>>(id_logits, soft_labels, entropy_w, labels,
                                adv_logits, mod_labels,
                                id_features, gray_features,
                                epoch, (float*)d_out);
}